// round 13
// baseline (speedup 1.0000x reference)
#include <cuda_runtime.h>
#include <cuda_fp16.h>
#include <math.h>
#include <stdint.h>

#define NN 20000
#define NE 200000
#define NG 512

// ---------------- scratch (device globals; no allocation allowed) ----------------
__device__ float g_agg1[NN * 48];
__device__ float g_agg2[NN * 32];
__device__ float g_agg3[NN * 16];
__device__ float g_y1[NN * 48];
__device__ float g_y2[NN * 32];
__device__ float g_y3[NN * 16];
__device__ float g_deg[NN];
__device__ float g_ebuf[NN];
__device__ float g_hl[NG * 16];
__device__ float g_cl[NG * 16];
__device__ float g_ql[NG * 32];
__device__ unsigned g_emax[NG];
__device__ float g_asum[NG];
__device__ float g_rraw[NG * 16];
__device__ int g_cnt[NN];
__device__ int g_cur[NN];
__device__ int g_off[NN + 1];
__device__ int g_sorted[NE];

// ---------------- helpers ----------------
__device__ __forceinline__ float sigf(float x) { return 1.f / (1.f + expf(-x)); }

__device__ __forceinline__ unsigned fflip(float f) {
    unsigned u = __float_as_uint(f);
    return (u & 0x80000000u) ? ~u : (u | 0x80000000u);
}
__device__ __forceinline__ float funflip(unsigned u) {
    return (u & 0x80000000u) ? __uint_as_float(u & 0x7fffffffu) : __uint_as_float(~u);
}

__global__ void k_histdeg(const int* __restrict__ ei, float* deg, int* cnt) {
    int e = blockIdx.x * blockDim.x + threadIdx.x;
    if (e < NE) {
        atomicAdd(&deg[ei[NE + e]], 1.f);
        atomicAdd(&cnt[ei[e]], 1);
    }
}

__global__ void k_scan(int* __restrict__ cnt, int* __restrict__ cur,
                       int* __restrict__ off) {
    __shared__ int ssum[1024];
    int t = threadIdx.x;
    int base = t * 20;
    int loc[20];
    int s = 0;
#pragma unroll
    for (int k = 0; k < 20; k++) {
        int idx = base + k;
        int v = (idx < NN) ? cnt[idx] : 0;
        if (idx < NN) cnt[idx] = 0;
        loc[k] = s;
        s += v;
    }
    ssum[t] = s;
    __syncthreads();
    for (int d = 1; d < 1024; d <<= 1) {
        int v = (t >= d) ? ssum[t - d] : 0;
        __syncthreads();
        ssum[t] += v;
        __syncthreads();
    }
    int boff = (t > 0) ? ssum[t - 1] : 0;
#pragma unroll
    for (int k = 0; k < 20; k++) {
        int idx = base + k;
        if (idx < NN) { cur[idx] = boff + loc[k]; off[idx] = boff + loc[k]; }
    }
    if (t == 1023) off[NN] = ssum[1023];
}

__global__ void k_scatterE(const int* __restrict__ ei, int* cur, int* __restrict__ sorted,
                           float* __restrict__ agg1, float* __restrict__ agg2,
                           float* __restrict__ agg3) {
    int idx = blockIdx.x * blockDim.x + threadIdx.x;
    int stride = gridDim.x * blockDim.x;
    for (int i = idx; i < NN * 48; i += stride) agg1[i] = 0.f;
    for (int i = idx; i < NN * 32; i += stride) agg2[i] = 0.f;
    for (int i = idx; i < NN * 16; i += stride) agg3[i] = 0.f;
    if (idx < NE) {
        int p = atomicAdd(&cur[ei[idx]], 1);
        sorted[p] = idx;
    }
}

// ---------------- fused NNConv message pass ----------------
// Per-layer tuned via MINCTA / HALFM. Build uses float4 xg broadcasts
// (4x fewer xg LDS than R12) and float4 W2 o-quads with fp32 accumulate.
template <int IC, int OC, int G, int EC, int MINCTA, bool HALFM>
__global__ __launch_bounds__(512, MINCTA)
void k_fused(const float* __restrict__ x, const float* __restrict__ ea,
             const int* __restrict__ ei, const int* __restrict__ sorted,
             const int* __restrict__ off,
             const float* __restrict__ W1, const float* __restrict__ b1,
             const float* __restrict__ W2, const float* __restrict__ b2,
             float* __restrict__ agg) {
    extern __shared__ float sm[];
    float* W1s = sm;                            // 2048 floats
    float* b1s = W1s + 2048;                    // 128
    float* hs  = b1s + 128;                     // 16 * EC * 128
    float* xg  = hs + 16 * EC * 128;            // G * IC (16B-aligned: IC%4==0)
    float* Bs  = xg + G * IC;                   // G * OC
    int*  offs = (int*)(Bs + G * OC);           // padded to 4-int multiple
    void* Mbase = (void*)(offs + ((G + 4) & ~3));
    __half* Mh = (__half*)Mbase;
    float*  Mf = (float*)Mbase;

    int t = threadIdx.x;
    int n0 = blockIdx.x * G;

    for (int idx = t; idx < 2048; idx += 512) W1s[idx] = W1[idx];
    if (t < 128) b1s[t] = b1[t];
    if (t <= G) {
        int n = n0 + t;
        offs[t] = off[n < NN ? n : NN];
    }
    for (int idx = t; idx < G * IC; idx += 512) {
        int g = idx / IC, i = idx % IC;
        int n = n0 + g;
        xg[idx] = (n < NN) ? x[(size_t)n * IC + i] : 0.f;
    }
    __syncthreads();

    // per-node bias term B[g,o] = sum_i x[g,i]*b2[i,o]
    for (int idx = t; idx < G * OC; idx += 512) {
        int g = idx / OC, o = idx % OC;
        float a = 0.f;
#pragma unroll
        for (int i = 0; i < IC; i++) a = fmaf(xg[g * IC + i], b2[(size_t)i * OC + o], a);
        Bs[idx] = a;
    }

    // M build: float4 W2 o-quads + float4 xg broadcasts, fp32 accumulate.
    constexpr int OQ = OC / 4;
    constexpr int GB = HALFM ? ((G > 5) ? 5 : G) : G;
    for (int g0 = 0; g0 < G; g0 += GB) {
        int gcnt = (G - g0 < GB) ? (G - g0) : GB;
        for (int q = t; q < 128 * OQ; q += 512) {
            int p = q / OQ, oq = q % OQ;
            const float4* w2p = reinterpret_cast<const float4*>(W2 + (size_t)p * IC * OC) + oq;
            float4 acc[GB];
#pragma unroll
            for (int g = 0; g < GB; g++) acc[g] = make_float4(0.f, 0.f, 0.f, 0.f);
#pragma unroll
            for (int i4 = 0; i4 < IC; i4 += 4) {
                float4 w0 = w2p[(size_t)(i4 + 0) * OQ];
                float4 w1v = w2p[(size_t)(i4 + 1) * OQ];
                float4 w2v = w2p[(size_t)(i4 + 2) * OQ];
                float4 w3v = w2p[(size_t)(i4 + 3) * OQ];
#pragma unroll
                for (int g = 0; g < GB; g++) {
                    float4 xv = *reinterpret_cast<const float4*>(&xg[(g0 + g) * IC + i4]);
                    acc[g].x = fmaf(xv.x, w0.x, acc[g].x);
                    acc[g].y = fmaf(xv.x, w0.y, acc[g].y);
                    acc[g].z = fmaf(xv.x, w0.z, acc[g].z);
                    acc[g].w = fmaf(xv.x, w0.w, acc[g].w);
                    acc[g].x = fmaf(xv.y, w1v.x, acc[g].x);
                    acc[g].y = fmaf(xv.y, w1v.y, acc[g].y);
                    acc[g].z = fmaf(xv.y, w1v.z, acc[g].z);
                    acc[g].w = fmaf(xv.y, w1v.w, acc[g].w);
                    acc[g].x = fmaf(xv.z, w2v.x, acc[g].x);
                    acc[g].y = fmaf(xv.z, w2v.y, acc[g].y);
                    acc[g].z = fmaf(xv.z, w2v.z, acc[g].z);
                    acc[g].w = fmaf(xv.z, w2v.w, acc[g].w);
                    acc[g].x = fmaf(xv.w, w3v.x, acc[g].x);
                    acc[g].y = fmaf(xv.w, w3v.y, acc[g].y);
                    acc[g].z = fmaf(xv.w, w3v.z, acc[g].z);
                    acc[g].w = fmaf(xv.w, w3v.w, acc[g].w);
                }
            }
            for (int g = 0; g < gcnt; g++) {
                size_t cidx = (size_t)(g0 + g) * 128 * OC + p * OC + oq * 4;
                if (HALFM) {
                    __half2 h01 = __floats2half2_rn(acc[g].x, acc[g].y);
                    __half2 h23 = __floats2half2_rn(acc[g].z, acc[g].w);
                    __half2* dst = reinterpret_cast<__half2*>(&Mh[cidx]);
                    dst[0] = h01;
                    dst[1] = h23;
                } else {
                    *reinterpret_cast<float4*>(&Mf[cidx]) = acc[g];
                }
            }
        }
    }
    __syncthreads();

    // ---------------- edge phase ----------------
    int warp = t >> 5, lane = t & 31;
    float* hw = hs + warp * EC * 128;
    const int OA = (OC < 32) ? OC : 32;
    int o_c = (OC == 16) ? (lane & 15) : ((lane < OA) ? lane : (OA - 1));
    int o2_c = (lane < 16) ? (32 + lane) : 47;      // OC==48 only
    int phalf = (OC == 16) ? ((lane >> 4) * 4) : 0; // OC==16: lane-half p split

    int ck = 0;
    for (int g = 0; g < G; g++) {
        int eb = offs[g], ee = offs[g + 1];
        size_t gbase = (size_t)g * 128 * OC;
        for (int c0 = eb; c0 < ee; c0 += EC, ck++) {
            if ((ck & 15) != warp) continue;
            int E = (ee - c0 < EC) ? (ee - c0) : EC;

            int tg[EC];
            for (int e = 0; e < E; e++) {
                int edge = sorted[c0 + e];
                tg[e] = ei[NE + edge];
                float ear[16];
                const float4* eav4 = reinterpret_cast<const float4*>(ea + (size_t)edge * 16);
#pragma unroll
                for (int k = 0; k < 4; k++) {
                    float4 v = eav4[k];
                    ear[4 * k + 0] = v.x; ear[4 * k + 1] = v.y;
                    ear[4 * k + 2] = v.z; ear[4 * k + 3] = v.w;
                }
#pragma unroll
                for (int k = 0; k < 4; k++) {
                    int p = lane + 32 * k;
                    float hv = b1s[p];
#pragma unroll
                    for (int i = 0; i < 16; i++) hv = fmaf(ear[i], W1s[i * 128 + p], hv);
                    hw[e * 128 + p] = fmaxf(hv, 0.f);
                }
            }
            __syncwarp();

            float acc[EC], acc2[EC];
#pragma unroll
            for (int e = 0; e < EC; e++) { acc[e] = 0.f; acc2[e] = 0.f; }

#define MLOAD(idx) (HALFM ? __half2float(Mh[gbase + (idx)]) : Mf[gbase + (idx)])
            if (OC == 16) {
                for (int p4 = phalf; p4 < 128; p4 += 8) {
                    float m0 = MLOAD((p4 + 0) * OC + o_c);
                    float m1 = MLOAD((p4 + 1) * OC + o_c);
                    float m2 = MLOAD((p4 + 2) * OC + o_c);
                    float m3 = MLOAD((p4 + 3) * OC + o_c);
#pragma unroll
                    for (int e = 0; e < EC; e++) {
                        if (e < E) {
                            float4 h4 = *reinterpret_cast<const float4*>(&hw[e * 128 + p4]);
                            acc[e] = fmaf(h4.x, m0, fmaf(h4.y, m1, fmaf(h4.z, m2, fmaf(h4.w, m3, acc[e]))));
                        }
                    }
                }
#pragma unroll
                for (int e = 0; e < EC; e++)
                    acc[e] += __shfl_down_sync(0xffffffffu, acc[e], 16);
            } else {
                for (int p4 = 0; p4 < 128; p4 += 4) {
                    float m0 = MLOAD((p4 + 0) * OC + o_c);
                    float m1 = MLOAD((p4 + 1) * OC + o_c);
                    float m2 = MLOAD((p4 + 2) * OC + o_c);
                    float m3 = MLOAD((p4 + 3) * OC + o_c);
                    float n0_, n1_, n2_, n3_;
                    if (OC == 48) {
                        n0_ = MLOAD((p4 + 0) * OC + o2_c);
                        n1_ = MLOAD((p4 + 1) * OC + o2_c);
                        n2_ = MLOAD((p4 + 2) * OC + o2_c);
                        n3_ = MLOAD((p4 + 3) * OC + o2_c);
                    }
#pragma unroll
                    for (int e = 0; e < EC; e++) {
                        if (e < E) {
                            float4 h4 = *reinterpret_cast<const float4*>(&hw[e * 128 + p4]);
                            acc[e] = fmaf(h4.x, m0, fmaf(h4.y, m1, fmaf(h4.z, m2, fmaf(h4.w, m3, acc[e]))));
                            if (OC == 48)
                                acc2[e] = fmaf(h4.x, n0_, fmaf(h4.y, n1_, fmaf(h4.z, n2_, fmaf(h4.w, n3_, acc2[e]))));
                        }
                    }
                }
            }
#undef MLOAD
            __syncwarp();

            for (int e = 0; e < E; e++) {
                if (OC == 16) {
                    if (lane < 16)
                        atomicAdd(&agg[(size_t)tg[e] * OC + lane], acc[e] + Bs[g * OC + lane]);
                } else {
                    if (lane < OA)
                        atomicAdd(&agg[(size_t)tg[e] * OC + lane], acc[e] + Bs[g * OC + lane]);
                    if (OC == 48 && lane < 16)
                        atomicAdd(&agg[(size_t)tg[e] * OC + 32 + lane], acc2[e] + Bs[g * OC + 32 + lane]);
                }
            }
        }
    }
}

// ---------------- node update: y = relu(agg/deg + x@root + bias) ----------------
__global__ void k_node(const float* __restrict__ agg, const float* __restrict__ deg,
                       const float* __restrict__ x, const float* __restrict__ root,
                       const float* __restrict__ bias, float* __restrict__ y,
                       int ic, int oc) {
    int idx = blockIdx.x * blockDim.x + threadIdx.x;
    if (idx >= NN * oc) return;
    int n = idx / oc, o = idx % oc;
    float a = agg[idx] / fmaxf(deg[n], 1.f) + bias[o];
    for (int i = 0; i < ic; i++) a = fmaf(x[(size_t)n * ic + i], root[i * oc + o], a);
    y[idx] = fmaxf(a, 0.f);
}

// ---------------- Set2Set ----------------
__global__ void k_lstm(const float* __restrict__ Wih, const float* __restrict__ Whh,
                       const float* __restrict__ bih, const float* __restrict__ bhh,
                       const float* __restrict__ q, float* __restrict__ h, float* __restrict__ c,
                       unsigned* __restrict__ emax, float* __restrict__ asum,
                       float* __restrict__ rraw) {
    int g = blockIdx.x * blockDim.x + threadIdx.x;
    if (g >= NG) return;
    float qs[32], hh[16], cc[16];
    for (int j = 0; j < 32; j++) qs[j] = q[g * 32 + j];
    for (int j = 0; j < 16; j++) { hh[j] = h[g * 16 + j]; cc[j] = c[g * 16 + j]; }
    float gates[64];
    for (int k = 0; k < 64; k++) {
        float a = bih[k] + bhh[k];
        for (int j = 0; j < 32; j++) a = fmaf(qs[j], Wih[k * 32 + j], a);
        for (int j = 0; j < 16; j++) a = fmaf(hh[j], Whh[k * 16 + j], a);
        gates[k] = a;
    }
    for (int j = 0; j < 16; j++) {
        float ig = sigf(gates[j]);
        float fg = sigf(gates[16 + j]);
        float gg = tanhf(gates[32 + j]);
        float og = sigf(gates[48 + j]);
        float cn = fg * cc[j] + ig * gg;
        float hn = og * tanhf(cn);
        c[g * 16 + j] = cn;
        h[g * 16 + j] = hn;
    }
    emax[g] = fflip(-1e30f);
    asum[g] = 0.f;
    for (int j = 0; j < 16; j++) rraw[g * 16 + j] = 0.f;
}

__global__ void k_attA(const float* __restrict__ y, const int* __restrict__ batch,
                       const float* __restrict__ hl, float* __restrict__ ebuf,
                       unsigned* __restrict__ emax) {
    int n = blockIdx.x * blockDim.x + threadIdx.x;
    if (n >= NN) return;
    int b = batch[n];
    float s = 0.f;
#pragma unroll
    for (int j = 0; j < 16; j++) s = fmaf(y[(size_t)n * 16 + j], hl[b * 16 + j], s);
    ebuf[n] = s;
    atomicMax(&emax[b], fflip(s));
}

__global__ void k_attB(const float* __restrict__ y, const int* __restrict__ batch,
                       const float* __restrict__ ebuf, const unsigned* __restrict__ emax,
                       float* __restrict__ asum, float* __restrict__ rraw) {
    int n = blockIdx.x * blockDim.x + threadIdx.x;
    if (n >= NN) return;
    int b = batch[n];
    float m = funflip(emax[b]);
    float a = expf(ebuf[n] - m);
    atomicAdd(&asum[b], a);
#pragma unroll
    for (int j = 0; j < 16; j++) atomicAdd(&rraw[b * 16 + j], a * y[(size_t)n * 16 + j]);
}

__global__ void k_fin(const float* __restrict__ h, const float* __restrict__ rraw,
                      const float* __restrict__ asum, float* __restrict__ q) {
    int g = blockIdx.x * blockDim.x + threadIdx.x;
    if (g >= NG) return;
    float s = fmaxf(asum[g], 1e-16f);
#pragma unroll
    for (int j = 0; j < 16; j++) {
        q[g * 32 + j] = h[g * 16 + j];
        q[g * 32 + 16 + j] = rraw[g * 16 + j] / s;
    }
}

// ---------------- head MLP (+ state recycle for next call) ----------------
__global__ void k_final(const float* __restrict__ q,
                        const float* __restrict__ l1W, const float* __restrict__ l1b,
                        const float* __restrict__ l2W, const float* __restrict__ l2b,
                        const float* __restrict__ lfW, const float* __restrict__ lfb,
                        float* __restrict__ out,
                        float* __restrict__ deg, float* __restrict__ hl,
                        float* __restrict__ cl, float* __restrict__ ql) {
    int g = blockIdx.x * blockDim.x + threadIdx.x;
    if (g < NN) deg[g] = 0.f;
    if (g >= NG) return;
    float t1[16];
    for (int o = 0; o < 16; o++) {
        float a = l1b[o];
        for (int j = 0; j < 32; j++) a = fmaf(q[g * 32 + j], l1W[j * 16 + o], a);
        t1[o] = fmaxf(a, 0.f);
    }
    float t2[8];
    for (int o = 0; o < 8; o++) {
        float a = l2b[o];
        for (int j = 0; j < 16; j++) a = fmaf(t1[j], l2W[j * 8 + o], a);
        t2[o] = fmaxf(a, 0.f);
    }
    float a = lfb[0];
    for (int j = 0; j < 8; j++) a = fmaf(t2[j], lfW[j], a);
    out[g] = a;
    for (int j = 0; j < 16; j++) { hl[g * 16 + j] = 0.f; cl[g * 16 + j] = 0.f; }
    for (int j = 0; j < 32; j++) ql[g * 32 + j] = 0.f;
}

// ---------------- host orchestration ----------------
template <int IC, int OC, int G, int EC, int MINCTA, bool HALFM>
static void run_layer(const float* xin, const float* ea, const int* ei,
                      const int* sorted, const int* off,
                      const float* W1, const float* b1, const float* W2,
                      const float* b2, const float* root, const float* bias,
                      float* yout, float* agg, const float* deg) {
    size_t smem = (size_t)(2048 + 128 + 16 * EC * 128 + G * IC + G * OC + ((G + 4) & ~3)) * 4
                + (size_t)G * 128 * OC * (HALFM ? 2 : 4);
    cudaFuncSetAttribute(k_fused<IC, OC, G, EC, MINCTA, HALFM>,
                         cudaFuncAttributeMaxDynamicSharedMemorySize, (int)smem);
    int grid = (NN + G - 1) / G;
    k_fused<IC, OC, G, EC, MINCTA, HALFM><<<grid, 512, smem>>>(
        xin, ea, ei, sorted, off, W1, b1, W2, b2, agg);
    k_node<<<(NN * OC + 255) / 256, 256>>>(agg, deg, xin, root, bias, yout, IC, OC);
}

extern "C" void kernel_launch(void* const* d_in, const int* in_sizes, int n_in,
                              void* d_out, int out_size) {
    const float* x = (const float*)d_in[0];
    const int* ei = (const int*)d_in[1];
    const float* ea = (const float*)d_in[2];
    const int* batch = (const int*)d_in[3];

    const float* c1_W1 = (const float*)d_in[4];
    const float* c1_b1 = (const float*)d_in[5];
    const float* c1_W2 = (const float*)d_in[6];
    const float* c1_b2 = (const float*)d_in[7];
    const float* c1_root = (const float*)d_in[8];
    const float* c1_bias = (const float*)d_in[9];

    const float* c2_W1 = (const float*)d_in[10];
    const float* c2_b1 = (const float*)d_in[11];
    const float* c2_W2 = (const float*)d_in[12];
    const float* c2_b2 = (const float*)d_in[13];
    const float* c2_root = (const float*)d_in[14];
    const float* c2_bias = (const float*)d_in[15];

    const float* c3_W1 = (const float*)d_in[16];
    const float* c3_b1 = (const float*)d_in[17];
    const float* c3_W2 = (const float*)d_in[18];
    const float* c3_b2 = (const float*)d_in[19];
    const float* c3_root = (const float*)d_in[20];
    const float* c3_bias = (const float*)d_in[21];

    const float* Wih = (const float*)d_in[22];
    const float* Whh = (const float*)d_in[23];
    const float* bih = (const float*)d_in[24];
    const float* bhh = (const float*)d_in[25];
    const float* l1W = (const float*)d_in[26];
    const float* l1b = (const float*)d_in[27];
    const float* l2W = (const float*)d_in[28];
    const float* l2b = (const float*)d_in[29];
    const float* lfW = (const float*)d_in[30];
    const float* lfb = (const float*)d_in[31];

    float* out = (float*)d_out;

    float *agg1, *agg2, *agg3, *y1, *y2, *y3, *deg, *ebuf, *hl, *cl, *ql, *asum, *rraw;
    unsigned* emax;
    int *cnt, *cur, *offp, *sorted;
    cudaGetSymbolAddress((void**)&agg1, g_agg1);
    cudaGetSymbolAddress((void**)&agg2, g_agg2);
    cudaGetSymbolAddress((void**)&agg3, g_agg3);
    cudaGetSymbolAddress((void**)&y1, g_y1);
    cudaGetSymbolAddress((void**)&y2, g_y2);
    cudaGetSymbolAddress((void**)&y3, g_y3);
    cudaGetSymbolAddress((void**)&deg, g_deg);
    cudaGetSymbolAddress((void**)&ebuf, g_ebuf);
    cudaGetSymbolAddress((void**)&hl, g_hl);
    cudaGetSymbolAddress((void**)&cl, g_cl);
    cudaGetSymbolAddress((void**)&ql, g_ql);
    cudaGetSymbolAddress((void**)&emax, g_emax);
    cudaGetSymbolAddress((void**)&asum, g_asum);
    cudaGetSymbolAddress((void**)&rraw, g_rraw);
    cudaGetSymbolAddress((void**)&cnt, g_cnt);
    cudaGetSymbolAddress((void**)&cur, g_cur);
    cudaGetSymbolAddress((void**)&offp, g_off);
    cudaGetSymbolAddress((void**)&sorted, g_sorted);

    // launch order: ncu captures the 4th launch -> k_fused L1
    k_histdeg<<<(NE + 255) / 256, 256>>>(ei, deg, cnt);
    k_scan<<<1, 1024>>>(cnt, cur, offp);
    k_scatterE<<<(NE + 255) / 256, 256>>>(ei, cur, sorted, agg1, agg2, agg3);

    // L1: fp16 M, 2 CTA/SM, G=5 (best measured config)
    run_layer<16, 48, 5, 4, 2, true>(x, ea, ei, sorted, offp, c1_W1, c1_b1, c1_W2, c1_b2,
                                     c1_root, c1_bias, y1, agg1, deg);
    // L2/L3: fp32 M, 1 CTA/SM, single-pass W2, max G under SMEM cap
    run_layer<48, 32, 11, 4, 1, false>(y1, ea, ei, sorted, offp, c2_W1, c2_b1, c2_W2, c2_b2,
                                       c2_root, c2_bias, y2, agg2, deg);
    run_layer<32, 16, 16, 4, 1, false>(y2, ea, ei, sorted, offp, c3_W1, c3_b1, c3_W2, c3_b2,
                                       c3_root, c3_bias, y3, agg3, deg);

    for (int s = 0; s < 2; s++) {
        k_lstm<<<2, 256>>>(Wih, Whh, bih, bhh, ql, hl, cl, emax, asum, rraw);
        k_attA<<<(NN + 255) / 256, 256>>>(y3, batch, hl, ebuf, emax);
        k_attB<<<(NN + 255) / 256, 256>>>(y3, batch, ebuf, emax, asum, rraw);
        k_fin<<<2, 256>>>(hl, rraw, asum, ql);
    }

    k_final<<<(NN + 255) / 256, 256>>>(ql, l1W, l1b, l2W, l2b, lfW, lfb, out,
                                       deg, hl, cl, ql);
}

// round 14
// speedup vs baseline: 2.7810x; 2.7810x over previous
#include <cuda_runtime.h>
#include <cuda_fp16.h>
#include <math.h>
#include <stdint.h>

#define NN 20000
#define NE 200000
#define NG 512

// ---------------- scratch (device globals; no allocation allowed) ----------------
__device__ float g_agg1[NN * 48];
__device__ float g_agg2[NN * 32];
__device__ float g_agg3[NN * 16];
__device__ float g_y1[NN * 48];
__device__ float g_y2[NN * 32];
__device__ float g_y3[NN * 16];
__device__ float g_deg[NN];
__device__ float g_ebuf[NN];
__device__ float g_hl[NG * 16];
__device__ float g_cl[NG * 16];
__device__ float g_ql[NG * 32];
__device__ unsigned g_emax[NG];
__device__ float g_asum[NG];
__device__ float g_rraw[NG * 16];
__device__ int g_cnt[NN];
__device__ int g_cur[NN];
__device__ int g_off[NN + 1];
__device__ int g_sorted[NE];

// ---------------- helpers ----------------
__device__ __forceinline__ float sigf(float x) { return 1.f / (1.f + expf(-x)); }

__device__ __forceinline__ unsigned fflip(float f) {
    unsigned u = __float_as_uint(f);
    return (u & 0x80000000u) ? ~u : (u | 0x80000000u);
}
__device__ __forceinline__ float funflip(unsigned u) {
    return (u & 0x80000000u) ? __uint_as_float(u & 0x7fffffffu) : __uint_as_float(~u);
}

__global__ void k_histdeg(const int* __restrict__ ei, float* deg, int* cnt) {
    int e = blockIdx.x * blockDim.x + threadIdx.x;
    if (e < NE) {
        atomicAdd(&deg[ei[NE + e]], 1.f);
        atomicAdd(&cnt[ei[e]], 1);
    }
}

__global__ void k_scan(int* __restrict__ cnt, int* __restrict__ cur,
                       int* __restrict__ off) {
    __shared__ int ssum[1024];
    int t = threadIdx.x;
    int base = t * 20;
    int loc[20];
    int s = 0;
#pragma unroll
    for (int k = 0; k < 20; k++) {
        int idx = base + k;
        int v = (idx < NN) ? cnt[idx] : 0;
        if (idx < NN) cnt[idx] = 0;
        loc[k] = s;
        s += v;
    }
    ssum[t] = s;
    __syncthreads();
    for (int d = 1; d < 1024; d <<= 1) {
        int v = (t >= d) ? ssum[t - d] : 0;
        __syncthreads();
        ssum[t] += v;
        __syncthreads();
    }
    int boff = (t > 0) ? ssum[t - 1] : 0;
#pragma unroll
    for (int k = 0; k < 20; k++) {
        int idx = base + k;
        if (idx < NN) { cur[idx] = boff + loc[k]; off[idx] = boff + loc[k]; }
    }
    if (t == 1023) off[NN] = ssum[1023];
}

__global__ void k_scatterE(const int* __restrict__ ei, int* cur, int* __restrict__ sorted,
                           float* __restrict__ agg1, float* __restrict__ agg2,
                           float* __restrict__ agg3) {
    int idx = blockIdx.x * blockDim.x + threadIdx.x;
    int stride = gridDim.x * blockDim.x;
    for (int i = idx; i < NN * 48; i += stride) agg1[i] = 0.f;
    for (int i = idx; i < NN * 32; i += stride) agg2[i] = 0.f;
    for (int i = idx; i < NN * 16; i += stride) agg3[i] = 0.f;
    if (idx < NE) {
        int p = atomicAdd(&cur[ei[idx]], 1);
        sorted[p] = idx;
    }
}

// ---------------- fused NNConv message pass ----------------
// R12 baseline (scalar xg build, per-layer MINCTA/HALFM) + one change:
// OC==48 second accumulator uses a lane-half p-split + shfl reduce, cutting
// its FMA and M-load work in half (no more discarded work in lanes 16-31).
template <int IC, int OC, int G, int EC, int MINCTA, bool HALFM>
__global__ __launch_bounds__(512, MINCTA)
void k_fused(const float* __restrict__ x, const float* __restrict__ ea,
             const int* __restrict__ ei, const int* __restrict__ sorted,
             const int* __restrict__ off,
             const float* __restrict__ W1, const float* __restrict__ b1,
             const float* __restrict__ W2, const float* __restrict__ b2,
             float* __restrict__ agg) {
    extern __shared__ float sm[];
    float* W1s = sm;                            // 2048 floats
    float* b1s = W1s + 2048;                    // 128
    float* hs  = b1s + 128;                     // 16 * EC * 128
    float* xg  = hs + 16 * EC * 128;            // G * IC
    float* Bs  = xg + G * IC;                   // G * OC
    int*  offs = (int*)(Bs + G * OC);           // padded to 4-int multiple
    void* Mbase = (void*)(offs + ((G + 4) & ~3));
    __half* Mh = (__half*)Mbase;                // if HALFM
    float*  Mf = (float*)Mbase;                 // if !HALFM

    int t = threadIdx.x;
    int n0 = blockIdx.x * G;

    for (int idx = t; idx < 2048; idx += 512) W1s[idx] = W1[idx];
    if (t < 128) b1s[t] = b1[t];
    if (t <= G) {
        int n = n0 + t;
        offs[t] = off[n < NN ? n : NN];
    }
    for (int idx = t; idx < G * IC; idx += 512) {
        int g = idx / IC, i = idx % IC;
        int n = n0 + g;
        xg[idx] = (n < NN) ? x[(size_t)n * IC + i] : 0.f;
    }
    __syncthreads();

    // per-node bias term B[g,o] = sum_i x[g,i]*b2[i,o]
    for (int idx = t; idx < G * OC; idx += 512) {
        int g = idx / OC, o = idx % OC;
        float a = 0.f;
#pragma unroll
        for (int i = 0; i < IC; i++) a = fmaf(xg[g * IC + i], b2[(size_t)i * OC + o], a);
        Bs[idx] = a;
    }

    // M build: fp32 W2 float4 o-quads, scalar xg broadcasts (R12-proven).
    constexpr int OQ = OC / 4;
    constexpr int GB = HALFM ? ((G > 5) ? 5 : G) : G;
    for (int g0 = 0; g0 < G; g0 += GB) {
        int gcnt = (G - g0 < GB) ? (G - g0) : GB;
        for (int q = t; q < 128 * OQ; q += 512) {
            int p = q / OQ, oq = q % OQ;
            const float4* w2p = reinterpret_cast<const float4*>(W2 + (size_t)p * IC * OC) + oq;
            float4 acc[GB];
#pragma unroll
            for (int g = 0; g < GB; g++) acc[g] = make_float4(0.f, 0.f, 0.f, 0.f);
#pragma unroll 4
            for (int i = 0; i < IC; i++) {
                float4 w = w2p[(size_t)i * OQ];
#pragma unroll
                for (int g = 0; g < GB; g++) {
                    float xv = xg[(g0 + g) * IC + i];
                    acc[g].x = fmaf(xv, w.x, acc[g].x);
                    acc[g].y = fmaf(xv, w.y, acc[g].y);
                    acc[g].z = fmaf(xv, w.z, acc[g].z);
                    acc[g].w = fmaf(xv, w.w, acc[g].w);
                }
            }
            for (int g = 0; g < gcnt; g++) {
                size_t cidx = (size_t)(g0 + g) * 128 * OC + p * OC + oq * 4;
                if (HALFM) {
                    __half2 h01 = __floats2half2_rn(acc[g].x, acc[g].y);
                    __half2 h23 = __floats2half2_rn(acc[g].z, acc[g].w);
                    __half2* dst = reinterpret_cast<__half2*>(&Mh[cidx]);
                    dst[0] = h01;
                    dst[1] = h23;
                } else {
                    *reinterpret_cast<float4*>(&Mf[cidx]) = acc[g];
                }
            }
        }
    }
    __syncthreads();

    // ---------------- edge phase ----------------
    int warp = t >> 5, lane = t & 31;
    float* hw = hs + warp * EC * 128;
    const int OA = (OC < 32) ? OC : 32;
    int o_c = (OC == 16) ? (lane & 15) : ((lane < OA) ? lane : (OA - 1));
    int o2_c = 32 + (lane & 15);                    // OC==48 only (lane-half split)
    int phalf = (lane >> 4) * 4;                    // OC==16 p-split start
    int ph2 = (lane >> 4) * 64;                     // OC==48 acc2 p-half start

    int ck = 0;
    for (int g = 0; g < G; g++) {
        int eb = offs[g], ee = offs[g + 1];
        size_t gbase = (size_t)g * 128 * OC;
        for (int c0 = eb; c0 < ee; c0 += EC, ck++) {
            if ((ck & 15) != warp) continue;
            int E = (ee - c0 < EC) ? (ee - c0) : EC;

            int tg[EC];
            for (int e = 0; e < E; e++) {
                int edge = sorted[c0 + e];
                tg[e] = ei[NE + edge];
                float ear[16];
                const float4* eav4 = reinterpret_cast<const float4*>(ea + (size_t)edge * 16);
#pragma unroll
                for (int k = 0; k < 4; k++) {
                    float4 v = eav4[k];
                    ear[4 * k + 0] = v.x; ear[4 * k + 1] = v.y;
                    ear[4 * k + 2] = v.z; ear[4 * k + 3] = v.w;
                }
#pragma unroll
                for (int k = 0; k < 4; k++) {
                    int p = lane + 32 * k;
                    float hv = b1s[p];
#pragma unroll
                    for (int i = 0; i < 16; i++) hv = fmaf(ear[i], W1s[i * 128 + p], hv);
                    hw[e * 128 + p] = fmaxf(hv, 0.f);
                }
            }
            __syncwarp();

            float acc[EC], acc2[EC];
#pragma unroll
            for (int e = 0; e < EC; e++) { acc[e] = 0.f; acc2[e] = 0.f; }

#define MLOAD(idx) (HALFM ? __half2float(Mh[gbase + (idx)]) : Mf[gbase + (idx)])
            if (OC == 16) {
                for (int p4 = phalf; p4 < 128; p4 += 8) {
                    float m0 = MLOAD((p4 + 0) * OC + o_c);
                    float m1 = MLOAD((p4 + 1) * OC + o_c);
                    float m2 = MLOAD((p4 + 2) * OC + o_c);
                    float m3 = MLOAD((p4 + 3) * OC + o_c);
#pragma unroll
                    for (int e = 0; e < EC; e++) {
                        if (e < E) {
                            float4 h4 = *reinterpret_cast<const float4*>(&hw[e * 128 + p4]);
                            acc[e] = fmaf(h4.x, m0, fmaf(h4.y, m1, fmaf(h4.z, m2, fmaf(h4.w, m3, acc[e]))));
                        }
                    }
                }
#pragma unroll
                for (int e = 0; e < EC; e++)
                    acc[e] += __shfl_down_sync(0xffffffffu, acc[e], 16);
            } else {
                // primary outputs: o = lane over all p
                for (int p4 = 0; p4 < 128; p4 += 4) {
                    float m0 = MLOAD((p4 + 0) * OC + o_c);
                    float m1 = MLOAD((p4 + 1) * OC + o_c);
                    float m2 = MLOAD((p4 + 2) * OC + o_c);
                    float m3 = MLOAD((p4 + 3) * OC + o_c);
#pragma unroll
                    for (int e = 0; e < EC; e++) {
                        if (e < E) {
                            float4 h4 = *reinterpret_cast<const float4*>(&hw[e * 128 + p4]);
                            acc[e] = fmaf(h4.x, m0, fmaf(h4.y, m1, fmaf(h4.z, m2, fmaf(h4.w, m3, acc[e]))));
                        }
                    }
                }
                if (OC == 48) {
                    // secondary outputs: o2 = 32 + (lane&15); lane-halves split p,
                    // then reduce across the halves.
                    for (int p4 = ph2; p4 < ph2 + 64; p4 += 4) {
                        float n0_ = MLOAD((p4 + 0) * OC + o2_c);
                        float n1_ = MLOAD((p4 + 1) * OC + o2_c);
                        float n2_ = MLOAD((p4 + 2) * OC + o2_c);
                        float n3_ = MLOAD((p4 + 3) * OC + o2_c);
#pragma unroll
                        for (int e = 0; e < EC; e++) {
                            if (e < E) {
                                float4 h4 = *reinterpret_cast<const float4*>(&hw[e * 128 + p4]);
                                acc2[e] = fmaf(h4.x, n0_, fmaf(h4.y, n1_,
                                          fmaf(h4.z, n2_, fmaf(h4.w, n3_, acc2[e]))));
                            }
                        }
                    }
#pragma unroll
                    for (int e = 0; e < EC; e++)
                        acc2[e] += __shfl_down_sync(0xffffffffu, acc2[e], 16);
                }
            }
#undef MLOAD
            __syncwarp();

            for (int e = 0; e < E; e++) {
                if (OC == 16) {
                    if (lane < 16)
                        atomicAdd(&agg[(size_t)tg[e] * OC + lane], acc[e] + Bs[g * OC + lane]);
                } else {
                    if (lane < OA)
                        atomicAdd(&agg[(size_t)tg[e] * OC + lane], acc[e] + Bs[g * OC + lane]);
                    if (OC == 48 && lane < 16)
                        atomicAdd(&agg[(size_t)tg[e] * OC + 32 + lane], acc2[e] + Bs[g * OC + 32 + lane]);
                }
            }
        }
    }
}

// ---------------- node update: y = relu(agg/deg + x@root + bias) ----------------
__global__ void k_node(const float* __restrict__ agg, const float* __restrict__ deg,
                       const float* __restrict__ x, const float* __restrict__ root,
                       const float* __restrict__ bias, float* __restrict__ y,
                       int ic, int oc) {
    int idx = blockIdx.x * blockDim.x + threadIdx.x;
    if (idx >= NN * oc) return;
    int n = idx / oc, o = idx % oc;
    float a = agg[idx] / fmaxf(deg[n], 1.f) + bias[o];
    for (int i = 0; i < ic; i++) a = fmaf(x[(size_t)n * ic + i], root[i * oc + o], a);
    y[idx] = fmaxf(a, 0.f);
}

// ---------------- Set2Set ----------------
__global__ void k_lstm(const float* __restrict__ Wih, const float* __restrict__ Whh,
                       const float* __restrict__ bih, const float* __restrict__ bhh,
                       const float* __restrict__ q, float* __restrict__ h, float* __restrict__ c,
                       unsigned* __restrict__ emax, float* __restrict__ asum,
                       float* __restrict__ rraw) {
    int g = blockIdx.x * blockDim.x + threadIdx.x;
    if (g >= NG) return;
    float qs[32], hh[16], cc[16];
    for (int j = 0; j < 32; j++) qs[j] = q[g * 32 + j];
    for (int j = 0; j < 16; j++) { hh[j] = h[g * 16 + j]; cc[j] = c[g * 16 + j]; }
    float gates[64];
    for (int k = 0; k < 64; k++) {
        float a = bih[k] + bhh[k];
        for (int j = 0; j < 32; j++) a = fmaf(qs[j], Wih[k * 32 + j], a);
        for (int j = 0; j < 16; j++) a = fmaf(hh[j], Whh[k * 16 + j], a);
        gates[k] = a;
    }
    for (int j = 0; j < 16; j++) {
        float ig = sigf(gates[j]);
        float fg = sigf(gates[16 + j]);
        float gg = tanhf(gates[32 + j]);
        float og = sigf(gates[48 + j]);
        float cn = fg * cc[j] + ig * gg;
        float hn = og * tanhf(cn);
        c[g * 16 + j] = cn;
        h[g * 16 + j] = hn;
    }
    emax[g] = fflip(-1e30f);
    asum[g] = 0.f;
    for (int j = 0; j < 16; j++) rraw[g * 16 + j] = 0.f;
}

__global__ void k_attA(const float* __restrict__ y, const int* __restrict__ batch,
                       const float* __restrict__ hl, float* __restrict__ ebuf,
                       unsigned* __restrict__ emax) {
    int n = blockIdx.x * blockDim.x + threadIdx.x;
    if (n >= NN) return;
    int b = batch[n];
    float s = 0.f;
#pragma unroll
    for (int j = 0; j < 16; j++) s = fmaf(y[(size_t)n * 16 + j], hl[b * 16 + j], s);
    ebuf[n] = s;
    atomicMax(&emax[b], fflip(s));
}

__global__ void k_attB(const float* __restrict__ y, const int* __restrict__ batch,
                       const float* __restrict__ ebuf, const unsigned* __restrict__ emax,
                       float* __restrict__ asum, float* __restrict__ rraw) {
    int n = blockIdx.x * blockDim.x + threadIdx.x;
    if (n >= NN) return;
    int b = batch[n];
    float m = funflip(emax[b]);
    float a = expf(ebuf[n] - m);
    atomicAdd(&asum[b], a);
#pragma unroll
    for (int j = 0; j < 16; j++) atomicAdd(&rraw[b * 16 + j], a * y[(size_t)n * 16 + j]);
}

__global__ void k_fin(const float* __restrict__ h, const float* __restrict__ rraw,
                      const float* __restrict__ asum, float* __restrict__ q) {
    int g = blockIdx.x * blockDim.x + threadIdx.x;
    if (g >= NG) return;
    float s = fmaxf(asum[g], 1e-16f);
#pragma unroll
    for (int j = 0; j < 16; j++) {
        q[g * 32 + j] = h[g * 16 + j];
        q[g * 32 + 16 + j] = rraw[g * 16 + j] / s;
    }
}

// ---------------- head MLP (+ state recycle for next call) ----------------
__global__ void k_final(const float* __restrict__ q,
                        const float* __restrict__ l1W, const float* __restrict__ l1b,
                        const float* __restrict__ l2W, const float* __restrict__ l2b,
                        const float* __restrict__ lfW, const float* __restrict__ lfb,
                        float* __restrict__ out,
                        float* __restrict__ deg, float* __restrict__ hl,
                        float* __restrict__ cl, float* __restrict__ ql) {
    int g = blockIdx.x * blockDim.x + threadIdx.x;
    if (g < NN) deg[g] = 0.f;
    if (g >= NG) return;
    float t1[16];
    for (int o = 0; o < 16; o++) {
        float a = l1b[o];
        for (int j = 0; j < 32; j++) a = fmaf(q[g * 32 + j], l1W[j * 16 + o], a);
        t1[o] = fmaxf(a, 0.f);
    }
    float t2[8];
    for (int o = 0; o < 8; o++) {
        float a = l2b[o];
        for (int j = 0; j < 16; j++) a = fmaf(t1[j], l2W[j * 8 + o], a);
        t2[o] = fmaxf(a, 0.f);
    }
    float a = lfb[0];
    for (int j = 0; j < 8; j++) a = fmaf(t2[j], lfW[j], a);
    out[g] = a;
    for (int j = 0; j < 16; j++) { hl[g * 16 + j] = 0.f; cl[g * 16 + j] = 0.f; }
    for (int j = 0; j < 32; j++) ql[g * 32 + j] = 0.f;
}

// ---------------- host orchestration ----------------
template <int IC, int OC, int G, int EC, int MINCTA, bool HALFM>
static void run_layer(const float* xin, const float* ea, const int* ei,
                      const int* sorted, const int* off,
                      const float* W1, const float* b1, const float* W2,
                      const float* b2, const float* root, const float* bias,
                      float* yout, float* agg, const float* deg) {
    size_t smem = (size_t)(2048 + 128 + 16 * EC * 128 + G * IC + G * OC + ((G + 4) & ~3)) * 4
                + (size_t)G * 128 * OC * (HALFM ? 2 : 4);
    cudaFuncSetAttribute(k_fused<IC, OC, G, EC, MINCTA, HALFM>,
                         cudaFuncAttributeMaxDynamicSharedMemorySize, (int)smem);
    int grid = (NN + G - 1) / G;
    k_fused<IC, OC, G, EC, MINCTA, HALFM><<<grid, 512, smem>>>(
        xin, ea, ei, sorted, off, W1, b1, W2, b2, agg);
    k_node<<<(NN * OC + 255) / 256, 256>>>(agg, deg, xin, root, bias, yout, IC, OC);
}

extern "C" void kernel_launch(void* const* d_in, const int* in_sizes, int n_in,
                              void* d_out, int out_size) {
    const float* x = (const float*)d_in[0];
    const int* ei = (const int*)d_in[1];
    const float* ea = (const float*)d_in[2];
    const int* batch = (const int*)d_in[3];

    const float* c1_W1 = (const float*)d_in[4];
    const float* c1_b1 = (const float*)d_in[5];
    const float* c1_W2 = (const float*)d_in[6];
    const float* c1_b2 = (const float*)d_in[7];
    const float* c1_root = (const float*)d_in[8];
    const float* c1_bias = (const float*)d_in[9];

    const float* c2_W1 = (const float*)d_in[10];
    const float* c2_b1 = (const float*)d_in[11];
    const float* c2_W2 = (const float*)d_in[12];
    const float* c2_b2 = (const float*)d_in[13];
    const float* c2_root = (const float*)d_in[14];
    const float* c2_bias = (const float*)d_in[15];

    const float* c3_W1 = (const float*)d_in[16];
    const float* c3_b1 = (const float*)d_in[17];
    const float* c3_W2 = (const float*)d_in[18];
    const float* c3_b2 = (const float*)d_in[19];
    const float* c3_root = (const float*)d_in[20];
    const float* c3_bias = (const float*)d_in[21];

    const float* Wih = (const float*)d_in[22];
    const float* Whh = (const float*)d_in[23];
    const float* bih = (const float*)d_in[24];
    const float* bhh = (const float*)d_in[25];
    const float* l1W = (const float*)d_in[26];
    const float* l1b = (const float*)d_in[27];
    const float* l2W = (const float*)d_in[28];
    const float* l2b = (const float*)d_in[29];
    const float* lfW = (const float*)d_in[30];
    const float* lfb = (const float*)d_in[31];

    float* out = (float*)d_out;

    float *agg1, *agg2, *agg3, *y1, *y2, *y3, *deg, *ebuf, *hl, *cl, *ql, *asum, *rraw;
    unsigned* emax;
    int *cnt, *cur, *offp, *sorted;
    cudaGetSymbolAddress((void**)&agg1, g_agg1);
    cudaGetSymbolAddress((void**)&agg2, g_agg2);
    cudaGetSymbolAddress((void**)&agg3, g_agg3);
    cudaGetSymbolAddress((void**)&y1, g_y1);
    cudaGetSymbolAddress((void**)&y2, g_y2);
    cudaGetSymbolAddress((void**)&y3, g_y3);
    cudaGetSymbolAddress((void**)&deg, g_deg);
    cudaGetSymbolAddress((void**)&ebuf, g_ebuf);
    cudaGetSymbolAddress((void**)&hl, g_hl);
    cudaGetSymbolAddress((void**)&cl, g_cl);
    cudaGetSymbolAddress((void**)&ql, g_ql);
    cudaGetSymbolAddress((void**)&emax, g_emax);
    cudaGetSymbolAddress((void**)&asum, g_asum);
    cudaGetSymbolAddress((void**)&rraw, g_rraw);
    cudaGetSymbolAddress((void**)&cnt, g_cnt);
    cudaGetSymbolAddress((void**)&cur, g_cur);
    cudaGetSymbolAddress((void**)&offp, g_off);
    cudaGetSymbolAddress((void**)&sorted, g_sorted);

    // launch order: ncu captures the 4th launch -> k_fused L1
    k_histdeg<<<(NE + 255) / 256, 256>>>(ei, deg, cnt);
    k_scan<<<1, 1024>>>(cnt, cur, offp);
    k_scatterE<<<(NE + 255) / 256, 256>>>(ei, cur, sorted, agg1, agg2, agg3);

    // L1: fp16 M, 2 CTA/SM, G=5 (best measured config)
    run_layer<16, 48, 5, 4, 2, true>(x, ea, ei, sorted, offp, c1_W1, c1_b1, c1_W2, c1_b2,
                                     c1_root, c1_bias, y1, agg1, deg);
    // L2/L3: fp32 M, 1 CTA/SM, single-pass W2 (exact R12 configs)
    run_layer<48, 32, 10, 4, 1, false>(y1, ea, ei, sorted, offp, c2_W1, c2_b1, c2_W2, c2_b2,
                                       c2_root, c2_bias, y2, agg2, deg);
    run_layer<32, 16, 16, 4, 1, false>(y2, ea, ei, sorted, offp, c3_W1, c3_b1, c3_W2, c3_b2,
                                       c3_root, c3_bias, y3, agg3, deg);

    for (int s = 0; s < 2; s++) {
        k_lstm<<<2, 256>>>(Wih, Whh, bih, bhh, ql, hl, cl, emax, asum, rraw);
        k_attA<<<(NN + 255) / 256, 256>>>(y3, batch, hl, ebuf, emax);
        k_attB<<<(NN + 255) / 256, 256>>>(y3, batch, ebuf, emax, asum, rraw);
        k_fin<<<2, 256>>>(hl, rraw, asum, ql);
    }

    k_final<<<(NN + 255) / 256, 256>>>(ql, l1W, l1b, l2W, l2b, lfW, lfb, out,
                                       deg, hl, cl, ql);
}